// round 1
// baseline (speedup 1.0000x reference)
#include <cuda_runtime.h>
#include <cuda_bf16.h>
#include <math.h>

// ---------------- problem constants ----------------
#define BSZ   2
#define LSEQ  1024
#define DIM   512
#define DI    1024          // EXP*DIM
#define DS    64
#define DTR   32
#define DC    4
#define NBLK  4             // NB
#define BSC   128           // BS = DIM/NB
#define ROWS  (BSZ*LSEQ)    // 2048
#define LAMB  0.01f

// ---------------- scratch (device globals, allowed) ----------------
__device__ float  g_ln  [ROWS*DIM];        // layernorm out
__device__ float  g_xz  [ROWS*2*DI];       // in_proj out (xm | z)
__device__ float  g_xmc [ROWS*DI];         // silu(conv(xm))
__device__ float  g_proj[ROWS*160];        // x_proj out (dt|B|C)
__device__ float  g_dt  [ROWS*DI];         // softplus dt
__device__ float  g_y   [ROWS*DI];         // scan out / gated
__device__ float2 g_cbuf[ROWS*DIM];        // complex fft buffer (B,N,4,128)
__device__ float  g_r1  [ROWS*DIM];
__device__ float  g_i1  [ROWS*DIM];

// ---------------- helpers ----------------
__device__ __forceinline__ float silu_f(float x){ return x / (1.f + expf(-x)); }
__device__ __forceinline__ float softplus_f(float x){ return x > 20.f ? x : log1pf(expf(x)); }
__device__ __forceinline__ float shrink_f(float x){
    return x > LAMB ? x - LAMB : (x < -LAMB ? x + LAMB : 0.f);
}

// ---------------- layernorm: one row (512) per block, 256 threads ----------------
__global__ void k_layernorm(const float* __restrict__ x, const float* __restrict__ w,
                            const float* __restrict__ b, float* __restrict__ out){
    int row = blockIdx.x;
    const float* xr = x + (size_t)row * DIM;
    int tid = threadIdx.x;
    float v0 = xr[tid], v1 = xr[tid + 256];
    float s = v0 + v1, q = v0*v0 + v1*v1;
    __shared__ float ss[8], sq[8];
    for (int o = 16; o; o >>= 1){ s += __shfl_down_sync(~0u, s, o); q += __shfl_down_sync(~0u, q, o); }
    if ((tid & 31) == 0){ ss[tid >> 5] = s; sq[tid >> 5] = q; }
    __syncthreads();
    __shared__ float mean_s, rstd_s;
    if (tid == 0){
        float S = 0.f, Q = 0.f;
        #pragma unroll
        for (int i = 0; i < 8; i++){ S += ss[i]; Q += sq[i]; }
        float m = S * (1.f/DIM);
        float var = Q * (1.f/DIM) - m*m;
        mean_s = m; rstd_s = rsqrtf(var + 1e-5f);
    }
    __syncthreads();
    float m = mean_s, r = rstd_s;
    out[(size_t)row*DIM + tid]       = (v0 - m)*r*w[tid]       + b[tid];
    out[(size_t)row*DIM + tid + 256] = (v1 - m)*r*w[tid + 256] + b[tid + 256];
}

// ---------------- generic fp32 GEMM: C[M,N] = A[M,K] @ B[N,K]^T ----------------
// epi: 0 = store, 1 = softplus(acc + bias[n]), 2 = C += acc
#define GBM 64
#define GBN 64
#define GBK 16
__global__ void k_gemm(int M, int N, int K,
                       const float* __restrict__ A, int lda,
                       const float* __restrict__ Bw, int ldb,
                       float* __restrict__ C, int ldc,
                       const float* __restrict__ bias, int epi){
    __shared__ float As[GBK][GBM + 4];
    __shared__ float Bs[GBK][GBN + 4];
    int tid = threadIdx.x;                  // 256
    int tx = tid & 15, ty = tid >> 4;
    int m0 = blockIdx.y * GBM, n0 = blockIdx.x * GBN;
    float acc[4][4] = {};

    for (int k0 = 0; k0 < K; k0 += GBK){
        #pragma unroll
        for (int i = 0; i < 4; i++){
            int e = tid + i * 256;
            int k = e & 15, r = e >> 4;
            int gk = k0 + k;
            int gm = m0 + r;
            As[k][r] = (gm < M && gk < K) ? A[(size_t)gm*lda + gk] : 0.f;
            int gn = n0 + r;
            Bs[k][r] = (gn < N && gk < K) ? Bw[(size_t)gn*ldb + gk] : 0.f;
        }
        __syncthreads();
        #pragma unroll
        for (int k = 0; k < GBK; k++){
            float a[4], bv[4];
            #pragma unroll
            for (int i = 0; i < 4; i++) a[i]  = As[k][ty*4 + i];
            #pragma unroll
            for (int j = 0; j < 4; j++) bv[j] = Bs[k][tx*4 + j];
            #pragma unroll
            for (int i = 0; i < 4; i++)
                #pragma unroll
                for (int j = 0; j < 4; j++)
                    acc[i][j] = fmaf(a[i], bv[j], acc[i][j]);
        }
        __syncthreads();
    }
    #pragma unroll
    for (int i = 0; i < 4; i++){
        int m = m0 + ty*4 + i;
        if (m >= M) continue;
        #pragma unroll
        for (int j = 0; j < 4; j++){
            int n = n0 + tx*4 + j;
            if (n >= N) continue;
            float v = acc[i][j];
            if (epi == 0)      C[(size_t)m*ldc + n] = v;
            else if (epi == 1) C[(size_t)m*ldc + n] = softplus_f(v + bias[n]);
            else               C[(size_t)m*ldc + n] += v;
        }
    }
}

// ---------------- causal depthwise conv (DC=4) + silu ----------------
__global__ void k_conv_silu(const float* __restrict__ conv_w, const float* __restrict__ conv_b){
    int idx = blockIdx.x * blockDim.x + threadIdx.x;
    if (idx >= ROWS * DI) return;
    int c = idx & (DI - 1);
    int l = (idx >> 10) & (LSEQ - 1);
    int b = idx >> 20;
    const float* xm = g_xz + (size_t)b * LSEQ * (2*DI);
    float acc = conv_b[c];
    #pragma unroll
    for (int k = 0; k < DC; k++){
        int lp = l + k - (DC - 1);
        if (lp >= 0) acc = fmaf(conv_w[c*DC + k], xm[(size_t)lp*(2*DI) + c], acc);
    }
    g_xmc[idx] = silu_f(acc);
}

// ---------------- selective scan: one warp per (b,d), 2 states/lane ----------------
__global__ void k_scan(const float* __restrict__ A_log){
    int warp = (blockIdx.x * blockDim.x + threadIdx.x) >> 5;   // 0..2047
    int lane = threadIdx.x & 31;
    int b = warp >> 10, d = warp & 1023;
    float A0 = -__expf(A_log[d*DS + lane]);
    float A1 = -__expf(A_log[d*DS + 32 + lane]);
    float h0 = 0.f, h1 = 0.f;
    for (int l = 0; l < LSEQ; l++){
        int row = b * LSEQ + l;
        float dtv = g_dt [(size_t)row*DI + d];
        float u   = g_xmc[(size_t)row*DI + d];
        const float* pr = g_proj + (size_t)row * 160;
        float Bv0 = pr[32 + lane],  Bv1 = pr[64 + lane];
        float Cv0 = pr[96 + lane],  Cv1 = pr[128 + lane];
        h0 = fmaf(__expf(dtv*A0), h0, dtv*Bv0*u);
        h1 = fmaf(__expf(dtv*A1), h1, dtv*Bv1*u);
        float yv = h0*Cv0 + h1*Cv1;
        #pragma unroll
        for (int o = 16; o; o >>= 1) yv += __shfl_down_sync(~0u, yv, o);
        if (lane == 0) g_y[(size_t)row*DI + d] = yv;
    }
}

// ---------------- y = (y + xmc*D) * silu(z) ----------------
__global__ void k_gate(const float* __restrict__ Dv){
    int idx = blockIdx.x * blockDim.x + threadIdx.x;
    if (idx >= ROWS * DI) return;
    int d = idx & (DI - 1);
    int row = idx >> 10;
    float z = g_xz[(size_t)row*(2*DI) + DI + d];
    float y = fmaf(g_xmc[idx], Dv[d], g_y[idx]);
    g_y[idx] = y * silu_f(z);
}

// ---------------- forward 4-point DFT along NB (real input) ----------------
__global__ void k_fft4_fwd(){
    int idx = blockIdx.x * blockDim.x + threadIdx.x;
    if (idx >= BSZ * LSEQ * BSC) return;
    int d = idx & 127;
    int row = idx >> 7;                  // b*1024 + n
    const float* p = g_ln + (size_t)row * DIM + d;
    float x0 = p[0], x1 = p[128], x2 = p[256], x3 = p[384];
    float2* q = g_cbuf + (size_t)row * DIM + d;
    q[0]   = make_float2(x0 + x1 + x2 + x3, 0.f);
    q[128] = make_float2(x0 - x2, -(x1 - x3));
    q[256] = make_float2(x0 - x1 + x2 - x3, 0.f);
    q[384] = make_float2(x0 - x2, x1 - x3);
}

// ---------------- radix-2 1024-pt FFT along N, one column per block ----------------
__global__ void k_fft1024(float sign){
    __shared__ float2 sh[1024];
    int col = blockIdx.x;                 // 0..1023
    int bi = col >> 9, ch = col & 511;
    float2* base = g_cbuf + (size_t)bi * LSEQ * DIM + ch;
    int tid = threadIdx.x;                // 512
    for (int i = tid; i < 1024; i += 512)
        sh[__brev((unsigned)i) >> 22] = base[(size_t)i * DIM];
    __syncthreads();
    for (int len = 2; len <= 1024; len <<= 1){
        int half = len >> 1;
        int j = tid & (half - 1);
        int i1 = ((tid & ~(half - 1)) << 1) | j;
        float ang = sign * 6.283185307179586f * (float)j / (float)len;
        float s, c;
        sincosf(ang, &s, &c);
        float2 a = sh[i1], bb = sh[i1 + half];
        float2 t = make_float2(bb.x*c - bb.y*s, bb.x*s + bb.y*c);
        __syncwarp();
        sh[i1]        = make_float2(a.x + t.x, a.y + t.y);
        sh[i1 + half] = make_float2(a.x - t.x, a.y - t.y);
        __syncthreads();
    }
    const float scale = 0.015625f;        // 1/64 (ortho for 1024*4, applied per direction)
    for (int i = tid; i < 1024; i += 512){
        float2 v = sh[i];
        base[(size_t)i * DIM] = make_float2(v.x * scale, v.y * scale);
    }
}

// ---------------- EinFFT complex layer 1: r1,i1 = relu(cplx mul + bias) ----------------
__global__ void k_cgemm1(const float* __restrict__ cw, const float* __restrict__ cb){
    extern __shared__ float sm[];
    float* sW0 = sm;                // 128*128
    float* sW1 = sm + 16384;        // 128*128
    float* sRe = sm + 32768;        // 32*128
    float* sIm = sm + 36864;        // 32*128
    int tid = threadIdx.x;          // 128
    int tile = blockIdx.x;          // 0..63
    int b = blockIdx.y;             // 0..3
    const float* W0 = cw + (size_t)b * 16384;
    const float* W1 = cw + (size_t)(4 + b) * 16384;
    for (int i = tid; i < 16384; i += 128){ sW0[i] = W0[i]; sW1[i] = W1[i]; }
    for (int i = tid; i < 4096; i += 128){
        int t2 = i >> 7, d = i & 127;
        float2 v = g_cbuf[(size_t)(tile*32 + t2) * DIM + b*BSC + d];
        sRe[i] = v.x; sIm[i] = v.y;
    }
    __syncthreads();
    int k = tid;
    float accR[32], accI[32];
    #pragma unroll
    for (int t = 0; t < 32; t++){ accR[t] = 0.f; accI[t] = 0.f; }
    for (int d = 0; d < 128; d++){
        float w0 = sW0[d*128 + k], w1 = sW1[d*128 + k];
        #pragma unroll
        for (int t = 0; t < 32; t++){
            float re = sRe[t*128 + d], im = sIm[t*128 + d];
            accR[t] = fmaf(re, w0, fmaf(-im, w1, accR[t]));
            accI[t] = fmaf(re, w1, fmaf( im, w0, accI[t]));
        }
    }
    float b0 = cb[b*BSC + k], b1 = cb[(4 + b)*BSC + k];
    #pragma unroll
    for (int t = 0; t < 32; t++){
        size_t o = (size_t)(tile*32 + t) * DIM + b*BSC + k;
        float rv = accR[t] + b0; g_r1[o] = rv > 0.f ? rv : 0.f;
        float iv = accI[t] + b1; g_i1[o] = iv > 0.f ? iv : 0.f;
    }
}

// ---------------- EinFFT complex layer 2: cbuf = softshrink(cplx mul + bias) ----------------
__global__ void k_cgemm2(const float* __restrict__ cw, const float* __restrict__ cb){
    extern __shared__ float sm[];
    float* sW0 = sm;
    float* sW1 = sm + 16384;
    float* sRe = sm + 32768;
    float* sIm = sm + 36864;
    int tid = threadIdx.x;
    int tile = blockIdx.x;
    int b = blockIdx.y;
    const float* W0 = cw + (size_t)b * 16384;
    const float* W1 = cw + (size_t)(4 + b) * 16384;
    for (int i = tid; i < 16384; i += 128){ sW0[i] = W0[i]; sW1[i] = W1[i]; }
    for (int i = tid; i < 4096; i += 128){
        int t2 = i >> 7, d = i & 127;
        size_t o = (size_t)(tile*32 + t2) * DIM + b*BSC + d;
        sRe[i] = g_r1[o]; sIm[i] = g_i1[o];
    }
    __syncthreads();
    int k = tid;
    float accR[32], accI[32];
    #pragma unroll
    for (int t = 0; t < 32; t++){ accR[t] = 0.f; accI[t] = 0.f; }
    for (int d = 0; d < 128; d++){
        float w0 = sW0[d*128 + k], w1 = sW1[d*128 + k];
        #pragma unroll
        for (int t = 0; t < 32; t++){
            float re = sRe[t*128 + d], im = sIm[t*128 + d];
            accR[t] = fmaf(re, w0, fmaf(-im, w1, accR[t]));
            accI[t] = fmaf(re, w1, fmaf( im, w0, accI[t]));
        }
    }
    float b0 = cb[b*BSC + k], b1 = cb[(4 + b)*BSC + k];
    #pragma unroll
    for (int t = 0; t < 32; t++){
        size_t o = (size_t)(tile*32 + t) * DIM + b*BSC + k;
        g_cbuf[o] = make_float2(shrink_f(accR[t] + b0), shrink_f(accI[t] + b1));
    }
}

// ---------------- inverse 4-point DFT along NB, take real, add into out ----------------
__global__ void k_fft4_inv_add(float* __restrict__ out){
    int idx = blockIdx.x * blockDim.x + threadIdx.x;
    if (idx >= BSZ * LSEQ * BSC) return;
    int d = idx & 127;
    int row = idx >> 7;
    const float2* q = g_cbuf + (size_t)row * DIM + d;
    float2 X0 = q[0], X1 = q[128], X2 = q[256], X3 = q[384];
    float* o = out + (size_t)row * DIM + d;
    // y_j = sum_k X_k * exp(+2*pi*i*j*k/4); real parts:
    o[0]   += X0.x + X1.x + X2.x + X3.x;
    o[128] += X0.x - X1.y - X2.x + X3.y;
    o[256] += X0.x - X1.x + X2.x - X3.x;
    o[384] += X0.x + X1.y - X2.x - X3.y;
}

// ---------------- host launch ----------------
extern "C" void kernel_launch(void* const* d_in, const int* in_sizes, int n_in,
                              void* d_out, int out_size){
    const float* x_in      = (const float*)d_in[0];
    const float* ln_w      = (const float*)d_in[1];
    const float* ln_b      = (const float*)d_in[2];
    const float* in_proj_w = (const float*)d_in[3];
    const float* conv_w    = (const float*)d_in[4];
    const float* conv_b    = (const float*)d_in[5];
    const float* x_proj_w  = (const float*)d_in[6];
    const float* dt_proj_w = (const float*)d_in[7];
    const float* dt_proj_b = (const float*)d_in[8];
    const float* A_log     = (const float*)d_in[9];
    const float* Dv        = (const float*)d_in[10];
    const float* out_proj_w= (const float*)d_in[11];
    const float* norm2_w   = (const float*)d_in[12];
    const float* norm2_b   = (const float*)d_in[13];
    const float* cw1       = (const float*)d_in[14];
    const float* cw2       = (const float*)d_in[15];
    const float* cb1       = (const float*)d_in[16];
    const float* cb2       = (const float*)d_in[17];
    float* xout = (float*)d_out;

    // scratch addresses
    float  *p_ln, *p_xz, *p_xmc, *p_proj, *p_dt, *p_y;
    cudaGetSymbolAddress((void**)&p_ln,   g_ln);
    cudaGetSymbolAddress((void**)&p_xz,   g_xz);
    cudaGetSymbolAddress((void**)&p_xmc,  g_xmc);
    cudaGetSymbolAddress((void**)&p_proj, g_proj);
    cudaGetSymbolAddress((void**)&p_dt,   g_dt);
    cudaGetSymbolAddress((void**)&p_y,    g_y);

    const size_t smemC = 40960 * sizeof(float);   // 160 KB
    cudaFuncSetAttribute(k_cgemm1, cudaFuncAttributeMaxDynamicSharedMemorySize, (int)smemC);
    cudaFuncSetAttribute(k_cgemm2, cudaFuncAttributeMaxDynamicSharedMemorySize, (int)smemC);

    // running residual lives in d_out
    cudaMemcpyAsync(xout, x_in, (size_t)ROWS*DIM*sizeof(float), cudaMemcpyDeviceToDevice, 0);

    dim3 gThr(256);
    for (int blk = 0; blk < 2; blk++){
        // ---- Mamba ----
        k_layernorm<<<ROWS, 256>>>(xout, ln_w, ln_b, p_ln);
        {   dim3 grid((2*DI + GBN - 1)/GBN, (ROWS + GBM - 1)/GBM);
            k_gemm<<<grid, 256>>>(ROWS, 2*DI, DIM, p_ln, DIM, in_proj_w, DIM, p_xz, 2*DI, nullptr, 0); }
        k_conv_silu<<<(ROWS*DI + 255)/256, gThr>>>(conv_w, conv_b);
        {   dim3 grid((160 + GBN - 1)/GBN, (ROWS + GBM - 1)/GBM);
            k_gemm<<<grid, 256>>>(ROWS, 160, DI, p_xmc, DI, x_proj_w, DI, p_proj, 160, nullptr, 0); }
        {   dim3 grid((DI + GBN - 1)/GBN, (ROWS + GBM - 1)/GBM);
            k_gemm<<<grid, 256>>>(ROWS, DI, DTR, p_proj, 160, dt_proj_w, DTR, p_dt, DI, dt_proj_b, 1); }
        k_scan<<<512, 128>>>(A_log);
        k_gate<<<(ROWS*DI + 255)/256, gThr>>>(Dv);
        {   dim3 grid((DIM + GBN - 1)/GBN, (ROWS + GBM - 1)/GBM);
            k_gemm<<<grid, 256>>>(ROWS, DIM, DI, p_y, DI, out_proj_w, DI, xout, DIM, nullptr, 2); }

        // ---- EinFFT ----
        k_layernorm<<<ROWS, 256>>>(xout, norm2_w, norm2_b, p_ln);
        k_fft4_fwd<<<(BSZ*LSEQ*BSC + 255)/256, gThr>>>();
        k_fft1024<<<1024, 512>>>(-1.f);
        {   dim3 grid(64, 4);
            k_cgemm1<<<grid, 128, smemC>>>(cw1, cb1); }
        {   dim3 grid(64, 4);
            k_cgemm2<<<grid, 128, smemC>>>(cw2, cb2); }
        k_fft1024<<<1024, 512>>>(1.f);
        k_fft4_inv_add<<<(BSZ*LSEQ*BSC + 255)/256, gThr>>>(xout);
    }
}

// round 2
// speedup vs baseline: 1.6366x; 1.6366x over previous
#include <cuda_runtime.h>
#include <cuda_bf16.h>
#include <math.h>

// ---------------- problem constants ----------------
#define BSZ   2
#define LSEQ  1024
#define DIM   512
#define DI    1024
#define DS    64
#define DTR   32
#define DC    4
#define ROWS  (BSZ*LSEQ)    // 2048
#define LAMB  0.01f

typedef unsigned long long u64;

// ---------------- scratch ----------------
__device__ float  g_ln  [ROWS*DIM];
__device__ float  g_xz  [ROWS*2*DI];
__device__ float  g_xmc [ROWS*DI];
__device__ float  g_proj[ROWS*160];
__device__ float  g_dt  [ROWS*DI];
__device__ float  g_y   [ROWS*DI];
__device__ float  g_fr  [ROWS*1024];   // split re|im spectral buffer [row][blk*256 + part*128 + j]
__device__ float  g_r1  [ROWS*1024];   // layer-1 activations (same layout)
__device__ float  g_W1  [4*256*256];
__device__ float  g_W2  [4*256*256];
__device__ float  g_b1  [4*256];
__device__ float  g_b2  [4*256];

// ---------------- f32x2 helpers ----------------
__device__ __forceinline__ u64 pk2(float a, float b){
    u64 r; asm("mov.b64 %0, {%1, %2};" : "=l"(r) : "f"(a), "f"(b)); return r;
}
__device__ __forceinline__ u64 fma2(u64 a, u64 b, u64 c){
    u64 d; asm("fma.rn.f32x2 %0, %1, %2, %3;" : "=l"(d) : "l"(a), "l"(b), "l"(c)); return d;
}
__device__ __forceinline__ float2 upk2(u64 v){
    float2 f; asm("mov.b64 {%0, %1}, %2;" : "=f"(f.x), "=f"(f.y) : "l"(v)); return f;
}

__device__ __forceinline__ float silu_f(float x){ return x / (1.f + expf(-x)); }
__device__ __forceinline__ float softplus_f(float x){ return x > 20.f ? x : log1pf(expf(x)); }
__device__ __forceinline__ float shrink_f(float x){
    return x > LAMB ? x - LAMB : (x < -LAMB ? x + LAMB : 0.f);
}

// ---------------- layernorm ----------------
__global__ void k_layernorm(const float* __restrict__ x, const float* __restrict__ w,
                            const float* __restrict__ b, float* __restrict__ out){
    int row = blockIdx.x;
    const float* xr = x + (size_t)row * DIM;
    int tid = threadIdx.x;
    float v0 = xr[tid], v1 = xr[tid + 256];
    float s = v0 + v1, q = v0*v0 + v1*v1;
    __shared__ float ss[8], sq[8];
    for (int o = 16; o; o >>= 1){ s += __shfl_down_sync(~0u, s, o); q += __shfl_down_sync(~0u, q, o); }
    if ((tid & 31) == 0){ ss[tid >> 5] = s; sq[tid >> 5] = q; }
    __syncthreads();
    __shared__ float mean_s, rstd_s;
    if (tid == 0){
        float S = 0.f, Q = 0.f;
        #pragma unroll
        for (int i = 0; i < 8; i++){ S += ss[i]; Q += sq[i]; }
        float m = S * (1.f/DIM);
        float var = Q * (1.f/DIM) - m*m;
        mean_s = m; rstd_s = rsqrtf(var + 1e-5f);
    }
    __syncthreads();
    float m = mean_s, r = rstd_s;
    out[(size_t)row*DIM + tid]       = (v0 - m)*r*w[tid]       + b[tid];
    out[(size_t)row*DIM + tid + 256] = (v1 - m)*r*w[tid + 256] + b[tid + 256];
}

// ---------------- templated f32x2 GEMM: C[M,N] = A[M,K] @ B[N,K]^T ----------------
// EPI: 0 store, 1 softplus(+bias), 2 +=, 3 relu(+bias), 4 softshrink(+bias)
template<int BM,int BN,int BK,int TM,int TN,int EPI>
__global__ void __launch_bounds__((BM/TM)*(BN/TN))
k_gemm_t(int K,
         const float* __restrict__ A, int lda, long long sAz,
         const float* __restrict__ Bw, int ldb, long long sBz,
         float* __restrict__ C, int ldc, long long sCz,
         const float* __restrict__ bias, long long sbz)
{
    constexpr int TX = BN/TN, TY = BM/TM, T = TX*TY;
    constexpr int K4 = BK/4;
    constexpr int NA = (BM*BK)/(4*T);
    constexpr int NB = (BN*BK)/(4*T);
    __shared__ float As[BK][BM+4];
    __shared__ float Bs[BK][BN+4];
    const int tid = threadIdx.x;
    const int tx = tid % TX, ty = tid / TX;
    const int m0 = blockIdx.y*BM, n0 = blockIdx.x*BN;
    A  += blockIdx.z * sAz;
    Bw += blockIdx.z * sBz;
    C  += blockIdx.z * sCz;
    if (bias) bias += blockIdx.z * sbz;
    const int mSub = ty*TM, nSub = tx*TN;

    u64 acc[TM][TN/2];
    #pragma unroll
    for (int i=0;i<TM;i++)
        #pragma unroll
        for (int j=0;j<TN/2;j++) acc[i][j]=0ULL;

    float4 ra[NA], rb[NB];
    // tile 0 loads
    #pragma unroll
    for (int l=0;l<NA;l++){ int e=tid+l*T; int am=e/K4, ak=(e%K4)*4;
        ra[l] = *(const float4*)(A + (size_t)(m0+am)*lda + ak); }
    #pragma unroll
    for (int l=0;l<NB;l++){ int e=tid+l*T; int bn=e/K4, bk=(e%K4)*4;
        rb[l] = *(const float4*)(Bw + (size_t)(n0+bn)*ldb + bk); }
    #pragma unroll
    for (int l=0;l<NA;l++){ int e=tid+l*T; int am=e/K4, ak=(e%K4)*4;
        As[ak+0][am]=ra[l].x; As[ak+1][am]=ra[l].y; As[ak+2][am]=ra[l].z; As[ak+3][am]=ra[l].w; }
    #pragma unroll
    for (int l=0;l<NB;l++){ int e=tid+l*T; int bn=e/K4, bk=(e%K4)*4;
        Bs[bk+0][bn]=rb[l].x; Bs[bk+1][bn]=rb[l].y; Bs[bk+2][bn]=rb[l].z; Bs[bk+3][bn]=rb[l].w; }
    __syncthreads();

    const int ntiles = K / BK;
    for (int t = 0; t < ntiles; t++){
        if (t+1 < ntiles){
            const float* Ap = A  + (size_t)(t+1)*BK;
            const float* Bp = Bw + (size_t)(t+1)*BK;
            #pragma unroll
            for (int l=0;l<NA;l++){ int e=tid+l*T; int am=e/K4, ak=(e%K4)*4;
                ra[l] = *(const float4*)(Ap + (size_t)(m0+am)*lda + ak); }
            #pragma unroll
            for (int l=0;l<NB;l++){ int e=tid+l*T; int bn=e/K4, bk=(e%K4)*4;
                rb[l] = *(const float4*)(Bp + (size_t)(n0+bn)*ldb + bk); }
        }
        #pragma unroll
        for (int k=0;k<BK;k++){
            float a[TM];
            #pragma unroll
            for (int i=0;i<TM;i+=4){
                float4 v = *(const float4*)&As[k][mSub+i];
                a[i]=v.x; a[i+1]=v.y; a[i+2]=v.z; a[i+3]=v.w;
            }
            u64 b2[TN/2];
            #pragma unroll
            for (int j=0;j<TN/2;j++) b2[j] = *(const u64*)&Bs[k][nSub+2*j];
            #pragma unroll
            for (int i=0;i<TM;i++){
                u64 a2 = pk2(a[i],a[i]);
                #pragma unroll
                for (int j=0;j<TN/2;j++) acc[i][j]=fma2(a2,b2[j],acc[i][j]);
            }
        }
        __syncthreads();
        if (t+1 < ntiles){
            #pragma unroll
            for (int l=0;l<NA;l++){ int e=tid+l*T; int am=e/K4, ak=(e%K4)*4;
                As[ak+0][am]=ra[l].x; As[ak+1][am]=ra[l].y; As[ak+2][am]=ra[l].z; As[ak+3][am]=ra[l].w; }
            #pragma unroll
            for (int l=0;l<NB;l++){ int e=tid+l*T; int bn=e/K4, bk=(e%K4)*4;
                Bs[bk+0][bn]=rb[l].x; Bs[bk+1][bn]=rb[l].y; Bs[bk+2][bn]=rb[l].z; Bs[bk+3][bn]=rb[l].w; }
            __syncthreads();
        }
    }

    #pragma unroll
    for (int i=0;i<TM;i++){
        float* crow = C + (size_t)(m0+mSub+i)*ldc + n0 + nSub;
        #pragma unroll
        for (int j=0;j<TN/2;j++){
            float2 v = upk2(acc[i][j]);
            int col = 2*j;
            if (EPI == 0){
                *(float2*)(crow+col) = v;
            } else if (EPI == 1){
                v.x = softplus_f(v.x + bias[n0+nSub+col]);
                v.y = softplus_f(v.y + bias[n0+nSub+col+1]);
                *(float2*)(crow+col) = v;
            } else if (EPI == 2){
                float2 o = *(float2*)(crow+col);
                o.x += v.x; o.y += v.y;
                *(float2*)(crow+col) = o;
            } else if (EPI == 3){
                v.x += bias[n0+nSub+col];   v.x = v.x > 0.f ? v.x : 0.f;
                v.y += bias[n0+nSub+col+1]; v.y = v.y > 0.f ? v.y : 0.f;
                *(float2*)(crow+col) = v;
            } else {
                v.x = shrink_f(v.x + bias[n0+nSub+col]);
                v.y = shrink_f(v.y + bias[n0+nSub+col+1]);
                *(float2*)(crow+col) = v;
            }
        }
    }
}

// ---------------- causal depthwise conv + silu ----------------
__global__ void k_conv_silu(const float* __restrict__ conv_w, const float* __restrict__ conv_b){
    int idx = blockIdx.x * blockDim.x + threadIdx.x;
    if (idx >= ROWS * DI) return;
    int c = idx & (DI - 1);
    int l = (idx >> 10) & (LSEQ - 1);
    int b = idx >> 20;
    const float* xm = g_xz + (size_t)b * LSEQ * (2*DI);
    float acc = conv_b[c];
    #pragma unroll
    for (int k = 0; k < DC; k++){
        int lp = l + k - (DC - 1);
        if (lp >= 0) acc = fmaf(conv_w[c*DC + k], xm[(size_t)lp*(2*DI) + c], acc);
    }
    g_xmc[idx] = silu_f(acc);
}

// ---------------- selective scan, warp per (b,d), 4-step load batching ----------------
__global__ void k_scan(const float* __restrict__ A_log){
    int warp = (blockIdx.x * blockDim.x + threadIdx.x) >> 5;
    int lane = threadIdx.x & 31;
    int b = warp >> 10, d = warp & 1023;
    float A0 = -__expf(A_log[d*DS + lane]);
    float A1 = -__expf(A_log[d*DS + 32 + lane]);
    const float* pdt = g_dt  + (size_t)b*LSEQ*DI + d;
    const float* pu  = g_xmc + (size_t)b*LSEQ*DI + d;
    const float* pp  = g_proj + (size_t)b*LSEQ*160;
    float* py        = g_y   + (size_t)b*LSEQ*DI + d;
    float h0 = 0.f, h1 = 0.f;
    for (int l0 = 0; l0 < LSEQ; l0 += 4){
        float dtv[4], u[4], B0[4], B1[4], C0[4], C1[4];
        #pragma unroll
        for (int s = 0; s < 4; s++){
            int l = l0 + s;
            dtv[s] = pdt[(size_t)l << 10];
            u[s]   = pu [(size_t)l << 10];
            const float* pr = pp + (size_t)l * 160;
            B0[s] = pr[32 + lane];  B1[s] = pr[64 + lane];
            C0[s] = pr[96 + lane];  C1[s] = pr[128 + lane];
        }
        #pragma unroll
        for (int s = 0; s < 4; s++){
            float du = dtv[s] * u[s];
            h0 = fmaf(__expf(dtv[s]*A0), h0, du * B0[s]);
            h1 = fmaf(__expf(dtv[s]*A1), h1, du * B1[s]);
            float yv = h0*C0[s] + h1*C1[s];
            #pragma unroll
            for (int o = 16; o; o >>= 1) yv += __shfl_down_sync(~0u, yv, o);
            if (lane == 0) py[(size_t)(l0+s) << 10] = yv;
        }
    }
}

// ---------------- y = (y + xmc*D) * silu(z) ----------------
__global__ void k_gate(const float* __restrict__ Dv){
    int idx = blockIdx.x * blockDim.x + threadIdx.x;
    if (idx >= ROWS * DI) return;
    int d = idx & (DI - 1);
    int row = idx >> 10;
    float z = g_xz[(size_t)row*(2*DI) + DI + d];
    float y = fmaf(g_xmc[idx], Dv[d], g_y[idx]);
    g_y[idx] = y * silu_f(z);
}

// ---------------- build EinFFT real-GEMM weights/biases (once per launch) ----------------
__global__ void k_build(const float* __restrict__ cw1, const float* __restrict__ cw2,
                        const float* __restrict__ cb1, const float* __restrict__ cb2){
    int idx = blockIdx.x * blockDim.x + threadIdx.x;
    if (idx >= 4*256*256) return;
    int k = idx & 255, n = (idx >> 8) & 255, b = idx >> 16;
    int j = n & 127, d = k & 127;
    bool nre = n < 128, kre = k < 128;
    float w0a = cw1[b*16384 + d*128 + j];
    float w1a = cw1[65536 + b*16384 + d*128 + j];
    g_W1[idx] = nre ? (kre ? w0a : -w1a) : (kre ? w1a : w0a);
    float w0b = cw2[b*16384 + d*128 + j];
    float w1b = cw2[65536 + b*16384 + d*128 + j];
    g_W2[idx] = nre ? (kre ? w0b : -w1b) : (kre ? w1b : w0b);
    if (k == 0){
        g_b1[b*256 + n] = nre ? cb1[b*128 + j] : cb1[512 + b*128 + j];
        g_b2[b*256 + n] = nre ? cb2[b*128 + j] : cb2[512 + b*128 + j];
    }
}

// ---------------- forward 4-point DFT along NB (real input) → split layout ----------------
__global__ void k_fft4_fwd(){
    int idx = blockIdx.x * blockDim.x + threadIdx.x;
    if (idx >= ROWS * 128) return;
    int j = idx & 127, row = idx >> 7;
    const float* p = g_ln + (size_t)row * DIM + j;
    float x0 = p[0], x1 = p[128], x2 = p[256], x3 = p[384];
    float* q = g_fr + (size_t)row * 1024 + j;
    q[0]   = x0 + x1 + x2 + x3;  q[128] = 0.f;
    q[256] = x0 - x2;            q[384] = -(x1 - x3);
    q[512] = x0 - x1 + x2 - x3;  q[640] = 0.f;
    q[768] = x0 - x2;            q[896] = x1 - x3;
}

// ---------------- 1024-pt radix-2 FFT along N, 8 columns per block, split layout ----------------
__global__ void k_fft1024s(float sign){
    extern __shared__ float2 sh[];   // [8][1025]
    const int tid = threadIdx.x;     // 512
    const int c = tid & 7, i0 = tid >> 3;
    int blk = blockIdx.x;            // 128 = 2b * 4kblk * 16j8
    int b = blk >> 6;
    int rem = blk & 63;
    int kblk = rem >> 4, j8 = rem & 15;
    float* base = g_fr + (size_t)b * 1024 * 1024 + kblk*256 + j8*8;

    #pragma unroll
    for (int r = 0; r < 16; r++){
        int n = i0 + r*64;
        int rv = __brev((unsigned)n) >> 22;
        float re = base[(size_t)n*1024 + c];
        float im = base[(size_t)n*1024 + 128 + c];
        sh[c*1025 + rv] = make_float2(re, im);
    }
    __syncthreads();
    for (int len = 2; len <= 1024; len <<= 1){
        int half = len >> 1;
        float w0 = sign * 6.283185307179586f / (float)len;
        #pragma unroll 2
        for (int r = 0; r < 8; r++){
            int bf = i0 + r*64;
            int j = bf & (half - 1);
            int i1 = ((bf & ~(half - 1)) << 1) | j;
            float s, cc;
            __sincosf(w0 * (float)j, &s, &cc);
            float2 av = sh[c*1025 + i1];
            float2 bv = sh[c*1025 + i1 + half];
            float2 t = make_float2(bv.x*cc - bv.y*s, bv.x*s + bv.y*cc);
            sh[c*1025 + i1]        = make_float2(av.x + t.x, av.y + t.y);
            sh[c*1025 + i1 + half] = make_float2(av.x - t.x, av.y - t.y);
        }
        __syncthreads();
    }
    const float sc = 0.015625f;   // 1/64 per direction (ortho over 1024*4)
    #pragma unroll
    for (int r = 0; r < 16; r++){
        int n = i0 + r*64;
        float2 v = sh[c*1025 + n];
        base[(size_t)n*1024 + c]       = v.x * sc;
        base[(size_t)n*1024 + 128 + c] = v.y * sc;
    }
}

// ---------------- inverse 4-point DFT along NB, real part, add into out ----------------
__global__ void k_fft4_inv_add(float* __restrict__ out){
    int idx = blockIdx.x * blockDim.x + threadIdx.x;
    if (idx >= ROWS * 128) return;
    int j = idx & 127, row = idx >> 7;
    const float* q = g_fr + (size_t)row * 1024 + j;
    float r0 = q[0];
    float r1 = q[256], i1 = q[384];
    float r2 = q[512];
    float r3 = q[768], i3 = q[896];
    float* o = out + (size_t)row * DIM + j;
    o[0]   += r0 + r1 + r2 + r3;
    o[128] += r0 - i1 - r2 + i3;
    o[256] += r0 - r1 + r2 - r3;
    o[384] += r0 + i1 - r2 - i3;
}

// ---------------- host launch ----------------
extern "C" void kernel_launch(void* const* d_in, const int* in_sizes, int n_in,
                              void* d_out, int out_size){
    const float* x_in      = (const float*)d_in[0];
    const float* ln_w      = (const float*)d_in[1];
    const float* ln_b      = (const float*)d_in[2];
    const float* in_proj_w = (const float*)d_in[3];
    const float* conv_w    = (const float*)d_in[4];
    const float* conv_b    = (const float*)d_in[5];
    const float* x_proj_w  = (const float*)d_in[6];
    const float* dt_proj_w = (const float*)d_in[7];
    const float* dt_proj_b = (const float*)d_in[8];
    const float* A_log     = (const float*)d_in[9];
    const float* Dv        = (const float*)d_in[10];
    const float* out_proj_w= (const float*)d_in[11];
    const float* norm2_w   = (const float*)d_in[12];
    const float* norm2_b   = (const float*)d_in[13];
    const float* cw1       = (const float*)d_in[14];
    const float* cw2       = (const float*)d_in[15];
    const float* cb1       = (const float*)d_in[16];
    const float* cb2       = (const float*)d_in[17];
    float* xout = (float*)d_out;

    float *p_ln, *p_xz, *p_xmc, *p_proj, *p_dt, *p_y, *p_fr, *p_r1, *p_W1, *p_W2, *p_b1, *p_b2;
    cudaGetSymbolAddress((void**)&p_ln,   g_ln);
    cudaGetSymbolAddress((void**)&p_xz,   g_xz);
    cudaGetSymbolAddress((void**)&p_xmc,  g_xmc);
    cudaGetSymbolAddress((void**)&p_proj, g_proj);
    cudaGetSymbolAddress((void**)&p_dt,   g_dt);
    cudaGetSymbolAddress((void**)&p_y,    g_y);
    cudaGetSymbolAddress((void**)&p_fr,   g_fr);
    cudaGetSymbolAddress((void**)&p_r1,   g_r1);
    cudaGetSymbolAddress((void**)&p_W1,   g_W1);
    cudaGetSymbolAddress((void**)&p_W2,   g_W2);
    cudaGetSymbolAddress((void**)&p_b1,   g_b1);
    cudaGetSymbolAddress((void**)&p_b2,   g_b2);

    cudaFuncSetAttribute(k_fft1024s, cudaFuncAttributeMaxDynamicSharedMemorySize, 8*1025*8);

    // residual lives in d_out
    cudaMemcpyAsync(xout, x_in, (size_t)ROWS*DIM*sizeof(float), cudaMemcpyDeviceToDevice, 0);
    // build EinFFT real-GEMM weights once
    k_build<<<(4*256*256 + 255)/256, 256>>>(cw1, cw2, cb1, cb2);

    for (int blk = 0; blk < 2; blk++){
        // ---- Mamba ----
        k_layernorm<<<ROWS, 256>>>(xout, ln_w, ln_b, p_ln);
        k_gemm_t<128,128,32,8,8,0><<<dim3(16,16,1), 256>>>(DIM,
            p_ln, DIM, 0, in_proj_w, DIM, 0, p_xz, 2*DI, 0, nullptr, 0);
        k_conv_silu<<<(ROWS*DI + 255)/256, 256>>>(conv_w, conv_b);
        k_gemm_t<64,32,32,4,4,0><<<dim3(5,32,1), 128>>>(DI,
            p_xmc, DI, 0, x_proj_w, DI, 0, p_proj, 160, 0, nullptr, 0);
        k_gemm_t<64,128,32,4,8,1><<<dim3(8,32,1), 256>>>(DTR,
            p_proj, 160, 0, dt_proj_w, DTR, 0, p_dt, DI, 0, dt_proj_b, 0);
        k_scan<<<512, 128>>>(A_log);
        k_gate<<<(ROWS*DI + 255)/256, 256>>>(Dv);
        k_gemm_t<64,128,32,4,8,2><<<dim3(4,32,1), 256>>>(DI,
            p_y, DI, 0, out_proj_w, DI, 0, xout, DIM, 0, nullptr, 0);

        // ---- EinFFT ----
        k_layernorm<<<ROWS, 256>>>(xout, norm2_w, norm2_b, p_ln);
        k_fft4_fwd<<<(ROWS*128 + 255)/256, 256>>>();
        k_fft1024s<<<128, 512, 8*1025*8>>>(-1.f);
        k_gemm_t<64,128,32,4,8,3><<<dim3(2,32,4), 256>>>(256,
            p_fr, 1024, 256, p_W1, 256, 65536, p_r1, 1024, 256, p_b1, 256);
        k_gemm_t<64,128,32,4,8,4><<<dim3(2,32,4), 256>>>(256,
            p_r1, 1024, 256, p_W2, 256, 65536, p_fr, 1024, 256, p_b2, 256);
        k_fft1024s<<<128, 512, 8*1025*8>>>(1.f);
        k_fft4_inv_add<<<(ROWS*128 + 255)/256, 256>>>(xout);
    }
}

// round 4
// speedup vs baseline: 2.2391x; 1.3681x over previous
#include <cuda_runtime.h>
#include <cuda_bf16.h>
#include <math.h>
#include <stdint.h>

// ---------------- problem constants ----------------
#define BSZ   2
#define LSEQ  1024
#define DIM   512
#define DI    1024
#define DS    64
#define DTR   32
#define DC    4
#define ROWS  (BSZ*LSEQ)    // 2048
#define LAMB  0.01f

typedef unsigned long long u64;

// ---------------- scratch ----------------
__device__ float  g_ln  [ROWS*DIM];
__device__ float  g_xz  [ROWS*2*DI];
__device__ float  g_xmc [ROWS*DI];
__device__ float  g_proj[ROWS*160];
__device__ float  g_dt  [ROWS*DI];
__device__ float  g_y   [ROWS*DI];
__device__ float  g_fr  [ROWS*1024];   // split re|im spectral buffer
__device__ float  g_r1  [ROWS*1024];
__device__ float  g_W1  [4*256*256];
__device__ float  g_W2  [4*256*256];
__device__ float  g_b1  [4*256];
__device__ float  g_b2  [4*256];
// bf16-extended weights (hi/lo interleaved along K: [n][2k]=hi, [n][2k+1]=lo)
__device__ __nv_bfloat16 g_wie[2048*1024];
__device__ __nv_bfloat16 g_woe[512*2048];
__device__ __nv_bfloat16 g_wde[1024*64];
__device__ __nv_bfloat16 g_w1e[4*256*512];
__device__ __nv_bfloat16 g_w2e[4*256*512];

// ---------------- f32x2 helpers ----------------
__device__ __forceinline__ u64 pk2(float a, float b){
    u64 r; asm("mov.b64 %0, {%1, %2};" : "=l"(r) : "f"(a), "f"(b)); return r;
}
__device__ __forceinline__ u64 fma2(u64 a, u64 b, u64 c){
    u64 d; asm("fma.rn.f32x2 %0, %1, %2, %3;" : "=l"(d) : "l"(a), "l"(b), "l"(c)); return d;
}
__device__ __forceinline__ float2 upk2(u64 v){
    float2 f; asm("mov.b64 {%0, %1}, %2;" : "=f"(f.x), "=f"(f.y) : "l"(v)); return f;
}

__device__ __forceinline__ float silu_f(float x){ return x / (1.f + expf(-x)); }
__device__ __forceinline__ float softplus_f(float x){ return x > 20.f ? x : log1pf(expf(x)); }
__device__ __forceinline__ float shrink_f(float x){
    return x > LAMB ? x - LAMB : (x < -LAMB ? x + LAMB : 0.f);
}

// ---------------- mma helpers (baseline PTX, no arch-specific features) ----------------
__device__ __forceinline__ uint32_t s2u(const void* p){
    uint32_t a;
    asm("{ .reg .u64 t; cvta.to.shared.u64 t, %1; cvt.u32.u64 %0, t; }" : "=r"(a) : "l"(p));
    return a;
}
__device__ __forceinline__ void ldsm4(uint32_t* r, uint32_t addr){
    asm volatile("ldmatrix.sync.aligned.m8n8.x4.shared.b16 {%0,%1,%2,%3}, [%4];"
        : "=r"(r[0]), "=r"(r[1]), "=r"(r[2]), "=r"(r[3]) : "r"(addr));
}
__device__ __forceinline__ void mma_bf16(float* c, const uint32_t* a, const uint32_t* b){
    asm volatile("mma.sync.aligned.m16n8k16.row.col.f32.bf16.bf16.f32 "
        "{%0,%1,%2,%3}, {%4,%5,%6,%7}, {%8,%9}, {%0,%1,%2,%3};"
        : "+f"(c[0]), "+f"(c[1]), "+f"(c[2]), "+f"(c[3])
        : "r"(a[0]), "r"(a[1]), "r"(a[2]), "r"(a[3]), "r"(b[0]), "r"(b[1]));
}
// split one float4 into 8 bf16 (hi/lo interleaved)
__device__ __forceinline__ uint4 ext8(float4 v){
    union { uint4 u; __nv_bfloat16 h[8]; } r;
    float xs[4] = {v.x, v.y, v.z, v.w};
    #pragma unroll
    for (int i = 0; i < 4; i++){
        __nv_bfloat16 hi = __float2bfloat16_rn(xs[i]);
        r.h[2*i]   = hi;
        r.h[2*i+1] = __float2bfloat16_rn(xs[i] - __bfloat162float(hi));
    }
    return r.u;
}

// ---------------- tensor-core bf16-split GEMM: C[M,N] = A[M,K] @ B[N,K]^T ----------------
// A: f32, converted on the fly. Bw: pre-extended bf16 [N][Kext], Kext = 2K.
// CTA tile 128x128, chunk = 32 ext-K (16 orig K). M,N multiples of 128, Kext multiple of 32.
// EPI: 0 store, 1 softplus(+bias), 2 +=, 3 relu(+bias), 4 softshrink(+bias)
template<int EPI>
__global__ void __launch_bounds__(256)
k_hgemm(int Kext,
        const float* __restrict__ A, int lda, long long sAz,
        const __nv_bfloat16* __restrict__ Bw, int ldbe, long long sBz,
        float* __restrict__ C, int ldc, long long sCz,
        const float* __restrict__ bias, long long sbz)
{
    __shared__ __align__(16) __nv_bfloat16 As[128][40];
    __shared__ __align__(16) __nv_bfloat16 Bs[128][40];
    const int tid = threadIdx.x, lane = tid & 31, wid = tid >> 5;
    const int wy = wid >> 2, wx = wid & 3;
    const int m0 = blockIdx.y * 128, n0 = blockIdx.x * 128;
    A  += blockIdx.z * sAz;
    Bw += blockIdx.z * sBz;
    C  += blockIdx.z * sCz;
    if (EPI == 1 || EPI == 3 || EPI == 4) bias += blockIdx.z * sbz;

    float acc[4][4][4] = {};
    const int arow = tid >> 2, acol = tid & 3;     // A: 4 float4 per 16-f32 row
    const int brow = tid >> 1, bq = (tid & 1) * 2; // B: 4 uint4 per 32-bf16 row

    const int nch = Kext >> 5;
    float4 pa0, pa1; uint4 pb0, pb1;

    // chunk 0 load
    {
        pa0 = *(const float4*)(A + (size_t)(m0+arow)*lda + acol*4);
        pa1 = *(const float4*)(A + (size_t)(m0+arow+64)*lda + acol*4);
        pb0 = *(const uint4*)(Bw + (size_t)(n0+brow)*ldbe + bq*8);
        pb1 = *(const uint4*)(Bw + (size_t)(n0+brow)*ldbe + (bq+1)*8);
    }
    *(uint4*)&As[arow][acol*8]    = ext8(pa0);
    *(uint4*)&As[arow+64][acol*8] = ext8(pa1);
    *(uint4*)&Bs[brow][bq*8]      = pb0;
    *(uint4*)&Bs[brow][(bq+1)*8]  = pb1;
    __syncthreads();

    const uint32_t sA = s2u(&As[0][0]), sB = s2u(&Bs[0][0]);
    const int q = lane >> 3, r = lane & 7;

    for (int ch = 0; ch < nch; ch++){
        if (ch + 1 < nch){
            int k0o = (ch+1) * 16, k0e = (ch+1) * 32;
            pa0 = *(const float4*)(A + (size_t)(m0+arow)*lda + k0o + acol*4);
            pa1 = *(const float4*)(A + (size_t)(m0+arow+64)*lda + k0o + acol*4);
            pb0 = *(const uint4*)(Bw + (size_t)(n0+brow)*ldbe + k0e + bq*8);
            pb1 = *(const uint4*)(Bw + (size_t)(n0+brow)*ldbe + k0e + (bq+1)*8);
        }
        #pragma unroll
        for (int ks = 0; ks < 2; ks++){
            uint32_t af[4][4], bf2[2][4];
            #pragma unroll
            for (int mi = 0; mi < 4; mi++){
                int row = wy*64 + mi*16 + r + (q & 1)*8;
                int col = ks*16 + (q >> 1)*8;
                ldsm4(af[mi], sA + (uint32_t)(row*40 + col)*2);
            }
            #pragma unroll
            for (int nb = 0; nb < 2; nb++){
                int nrow = wx*32 + nb*16 + r + (q >> 1)*8;
                int ncol = ks*16 + (q & 1)*8;
                ldsm4(bf2[nb], sB + (uint32_t)(nrow*40 + ncol)*2);
            }
            #pragma unroll
            for (int mi = 0; mi < 4; mi++)
                #pragma unroll
                for (int ni = 0; ni < 4; ni++)
                    mma_bf16(acc[mi][ni], af[mi], &bf2[ni>>1][(ni&1)*2]);
        }
        __syncthreads();
        if (ch + 1 < nch){
            *(uint4*)&As[arow][acol*8]    = ext8(pa0);
            *(uint4*)&As[arow+64][acol*8] = ext8(pa1);
            *(uint4*)&Bs[brow][bq*8]      = pb0;
            *(uint4*)&Bs[brow][(bq+1)*8]  = pb1;
            __syncthreads();
        }
    }

    // epilogue: direct float2 stores
    #pragma unroll
    for (int mi = 0; mi < 4; mi++){
        #pragma unroll
        for (int ni = 0; ni < 4; ni++){
            int row = m0 + wy*64 + mi*16 + (lane >> 2);
            int col = n0 + wx*32 + ni*8 + (lane & 3)*2;
            #pragma unroll
            for (int h = 0; h < 2; h++){
                float2 v = make_float2(acc[mi][ni][2*h], acc[mi][ni][2*h+1]);
                float* dst = C + (size_t)(row + h*8)*ldc + col;
                if (EPI == 1){
                    v.x = softplus_f(v.x + bias[col]);
                    v.y = softplus_f(v.y + bias[col+1]);
                } else if (EPI == 2){
                    float2 o = *(const float2*)dst;
                    v.x += o.x; v.y += o.y;
                } else if (EPI == 3){
                    v.x = fmaxf(v.x + bias[col], 0.f);
                    v.y = fmaxf(v.y + bias[col+1], 0.f);
                } else if (EPI == 4){
                    v.x = shrink_f(v.x + bias[col]);
                    v.y = shrink_f(v.y + bias[col+1]);
                }
                *(float2*)dst = v;
            }
        }
    }
}

// ---------------- weight expansion: f32 -> bf16 hi/lo interleaved ----------------
__global__ void k_wext(const float* __restrict__ src, __nv_bfloat16* __restrict__ dst, int n){
    int idx = blockIdx.x * blockDim.x + threadIdx.x;
    if (idx >= n) return;
    float x = src[idx];
    __nv_bfloat16 hi = __float2bfloat16_rn(x);
    dst[2*idx]   = hi;
    dst[2*idx+1] = __float2bfloat16_rn(x - __bfloat162float(hi));
}

// ---------------- layernorm ----------------
__global__ void k_layernorm(const float* __restrict__ x, const float* __restrict__ w,
                            const float* __restrict__ b, float* __restrict__ out){
    int row = blockIdx.x;
    const float* xr = x + (size_t)row * DIM;
    int tid = threadIdx.x;
    float v0 = xr[tid], v1 = xr[tid + 256];
    float s = v0 + v1, q = v0*v0 + v1*v1;
    __shared__ float ss[8], sq[8];
    for (int o = 16; o; o >>= 1){ s += __shfl_down_sync(~0u, s, o); q += __shfl_down_sync(~0u, q, o); }
    if ((tid & 31) == 0){ ss[tid >> 5] = s; sq[tid >> 5] = q; }
    __syncthreads();
    __shared__ float mean_s, rstd_s;
    if (tid == 0){
        float S = 0.f, Q = 0.f;
        #pragma unroll
        for (int i = 0; i < 8; i++){ S += ss[i]; Q += sq[i]; }
        float m = S * (1.f/DIM);
        float var = Q * (1.f/DIM) - m*m;
        mean_s = m; rstd_s = rsqrtf(var + 1e-5f);
    }
    __syncthreads();
    float m = mean_s, rr = rstd_s;
    out[(size_t)row*DIM + tid]       = (v0 - m)*rr*w[tid]       + b[tid];
    out[(size_t)row*DIM + tid + 256] = (v1 - m)*rr*w[tid + 256] + b[tid + 256];
}

// ---------------- SIMT f32x2 GEMM (x_proj only): C[M,N] = A[M,K] @ B[N,K]^T ----------------
template<int BM,int BN,int BK,int TM,int TN>
__global__ void __launch_bounds__((BM/TM)*(BN/TN))
k_gemm_t(int K,
         const float* __restrict__ A, int lda,
         const float* __restrict__ Bw, int ldb,
         float* __restrict__ C, int ldc)
{
    constexpr int TX = BN/TN, TY = BM/TM, T = TX*TY;
    constexpr int K4 = BK/4;
    constexpr int NA = (BM*BK)/(4*T);
    constexpr int NB = (BN*BK)/(4*T);
    __shared__ float As[BK][BM+4];
    __shared__ float Bs[BK][BN+4];
    const int tid = threadIdx.x;
    const int tx = tid % TX, ty = tid / TX;
    const int m0 = blockIdx.y*BM, n0 = blockIdx.x*BN;
    const int mSub = ty*TM, nSub = tx*TN;

    u64 acc[TM][TN/2];
    #pragma unroll
    for (int i=0;i<TM;i++)
        #pragma unroll
        for (int j=0;j<TN/2;j++) acc[i][j]=0ULL;

    float4 ra[NA], rb[NB];
    #pragma unroll
    for (int l=0;l<NA;l++){ int e=tid+l*T; int am=e/K4, ak=(e%K4)*4;
        ra[l] = *(const float4*)(A + (size_t)(m0+am)*lda + ak); }
    #pragma unroll
    for (int l=0;l<NB;l++){ int e=tid+l*T; int bn=e/K4, bk=(e%K4)*4;
        rb[l] = *(const float4*)(Bw + (size_t)(n0+bn)*ldb + bk); }
    #pragma unroll
    for (int l=0;l<NA;l++){ int e=tid+l*T; int am=e/K4, ak=(e%K4)*4;
        As[ak+0][am]=ra[l].x; As[ak+1][am]=ra[l].y; As[ak+2][am]=ra[l].z; As[ak+3][am]=ra[l].w; }
    #pragma unroll
    for (int l=0;l<NB;l++){ int e=tid+l*T; int bn=e/K4, bk=(e%K4)*4;
        Bs[bk+0][bn]=rb[l].x; Bs[bk+1][bn]=rb[l].y; Bs[bk+2][bn]=rb[l].z; Bs[bk+3][bn]=rb[l].w; }
    __syncthreads();

    const int ntiles = K / BK;
    for (int t = 0; t < ntiles; t++){
        if (t+1 < ntiles){
            const float* Ap = A  + (size_t)(t+1)*BK;
            const float* Bp = Bw + (size_t)(t+1)*BK;
            #pragma unroll
            for (int l=0;l<NA;l++){ int e=tid+l*T; int am=e/K4, ak=(e%K4)*4;
                ra[l] = *(const float4*)(Ap + (size_t)(m0+am)*lda + ak); }
            #pragma unroll
            for (int l=0;l<NB;l++){ int e=tid+l*T; int bn=e/K4, bk=(e%K4)*4;
                rb[l] = *(const float4*)(Bp + (size_t)(n0+bn)*ldb + bk); }
        }
        #pragma unroll
        for (int k=0;k<BK;k++){
            float a[TM];
            #pragma unroll
            for (int i=0;i<TM;i+=4){
                float4 v = *(const float4*)&As[k][mSub+i];
                a[i]=v.x; a[i+1]=v.y; a[i+2]=v.z; a[i+3]=v.w;
            }
            u64 b2[TN/2];
            #pragma unroll
            for (int j=0;j<TN/2;j++) b2[j] = *(const u64*)&Bs[k][nSub+2*j];
            #pragma unroll
            for (int i=0;i<TM;i++){
                u64 a2 = pk2(a[i],a[i]);
                #pragma unroll
                for (int j=0;j<TN/2;j++) acc[i][j]=fma2(a2,b2[j],acc[i][j]);
            }
        }
        __syncthreads();
        if (t+1 < ntiles){
            #pragma unroll
            for (int l=0;l<NA;l++){ int e=tid+l*T; int am=e/K4, ak=(e%K4)*4;
                As[ak+0][am]=ra[l].x; As[ak+1][am]=ra[l].y; As[ak+2][am]=ra[l].z; As[ak+3][am]=ra[l].w; }
            #pragma unroll
            for (int l=0;l<NB;l++){ int e=tid+l*T; int bn=e/K4, bk=(e%K4)*4;
                Bs[bk+0][bn]=rb[l].x; Bs[bk+1][bn]=rb[l].y; Bs[bk+2][bn]=rb[l].z; Bs[bk+3][bn]=rb[l].w; }
            __syncthreads();
        }
    }

    #pragma unroll
    for (int i=0;i<TM;i++){
        float* crow = C + (size_t)(m0+mSub+i)*ldc + n0 + nSub;
        #pragma unroll
        for (int j=0;j<TN/2;j++){
            float2 v = upk2(acc[i][j]);
            *(float2*)(crow+2*j) = v;
        }
    }
}

// ---------------- causal depthwise conv + silu ----------------
__global__ void k_conv_silu(const float* __restrict__ conv_w, const float* __restrict__ conv_b){
    int idx = blockIdx.x * blockDim.x + threadIdx.x;
    if (idx >= ROWS * DI) return;
    int c = idx & (DI - 1);
    int l = (idx >> 10) & (LSEQ - 1);
    int b = idx >> 20;
    const float* xm = g_xz + (size_t)b * LSEQ * (2*DI);
    float acc = conv_b[c];
    #pragma unroll
    for (int k = 0; k < DC; k++){
        int lp = l + k - (DC - 1);
        if (lp >= 0) acc = fmaf(conv_w[c*DC + k], xm[(size_t)lp*(2*DI) + c], acc);
    }
    g_xmc[idx] = silu_f(acc);
}

// ---------------- selective scan ----------------
__global__ void k_scan(const float* __restrict__ A_log){
    int warp = (blockIdx.x * blockDim.x + threadIdx.x) >> 5;
    int lane = threadIdx.x & 31;
    int b = warp >> 10, d = warp & 1023;
    float A0 = -__expf(A_log[d*DS + lane]);
    float A1 = -__expf(A_log[d*DS + 32 + lane]);
    const float* pdt = g_dt  + (size_t)b*LSEQ*DI + d;
    const float* pu  = g_xmc + (size_t)b*LSEQ*DI + d;
    const float* pp  = g_proj + (size_t)b*LSEQ*160;
    float* py        = g_y   + (size_t)b*LSEQ*DI + d;
    float h0 = 0.f, h1 = 0.f;
    for (int l0 = 0; l0 < LSEQ; l0 += 4){
        float dtv[4], u[4], B0[4], B1[4], C0[4], C1[4];
        #pragma unroll
        for (int s = 0; s < 4; s++){
            int l = l0 + s;
            dtv[s] = pdt[(size_t)l << 10];
            u[s]   = pu [(size_t)l << 10];
            const float* pr = pp + (size_t)l * 160;
            B0[s] = pr[32 + lane];  B1[s] = pr[64 + lane];
            C0[s] = pr[96 + lane];  C1[s] = pr[128 + lane];
        }
        #pragma unroll
        for (int s = 0; s < 4; s++){
            float du = dtv[s] * u[s];
            h0 = fmaf(__expf(dtv[s]*A0), h0, du * B0[s]);
            h1 = fmaf(__expf(dtv[s]*A1), h1, du * B1[s]);
            float yv = h0*C0[s] + h1*C1[s];
            #pragma unroll
            for (int o = 16; o; o >>= 1) yv += __shfl_down_sync(~0u, yv, o);
            if (lane == 0) py[(size_t)(l0+s) << 10] = yv;
        }
    }
}

// ---------------- y = (y + xmc*D) * silu(z) ----------------
__global__ void k_gate(const float* __restrict__ Dv){
    int idx = blockIdx.x * blockDim.x + threadIdx.x;
    if (idx >= ROWS * DI) return;
    int d = idx & (DI - 1);
    int row = idx >> 10;
    float z = g_xz[(size_t)row*(2*DI) + DI + d];
    float y = fmaf(g_xmc[idx], Dv[d], g_y[idx]);
    g_y[idx] = y * silu_f(z);
}

// ---------------- build EinFFT real-GEMM weights/biases ----------------
__global__ void k_build(const float* __restrict__ cw1, const float* __restrict__ cw2,
                        const float* __restrict__ cb1, const float* __restrict__ cb2){
    int idx = blockIdx.x * blockDim.x + threadIdx.x;
    if (idx >= 4*256*256) return;
    int k = idx & 255, n = (idx >> 8) & 255, b = idx >> 16;
    int j = n & 127, d = k & 127;
    bool nre = n < 128, kre = k < 128;
    float w0a = cw1[b*16384 + d*128 + j];
    float w1a = cw1[65536 + b*16384 + d*128 + j];
    g_W1[idx] = nre ? (kre ? w0a : -w1a) : (kre ? w1a : w0a);
    float w0b = cw2[b*16384 + d*128 + j];
    float w1b = cw2[65536 + b*16384 + d*128 + j];
    g_W2[idx] = nre ? (kre ? w0b : -w1b) : (kre ? w1b : w0b);
    if (k == 0){
        g_b1[b*256 + n] = nre ? cb1[b*128 + j] : cb1[512 + b*128 + j];
        g_b2[b*256 + n] = nre ? cb2[b*128 + j] : cb2[512 + b*128 + j];
    }
}

// ---------------- forward 4-point DFT along NB ----------------
__global__ void k_fft4_fwd(){
    int idx = blockIdx.x * blockDim.x + threadIdx.x;
    if (idx >= ROWS * 128) return;
    int j = idx & 127, row = idx >> 7;
    const float* p = g_ln + (size_t)row * DIM + j;
    float x0 = p[0], x1 = p[128], x2 = p[256], x3 = p[384];
    float* q = g_fr + (size_t)row * 1024 + j;
    q[0]   = x0 + x1 + x2 + x3;  q[128] = 0.f;
    q[256] = x0 - x2;            q[384] = -(x1 - x3);
    q[512] = x0 - x1 + x2 - x3;  q[640] = 0.f;
    q[768] = x0 - x2;            q[896] = x1 - x3;
}

// ---------------- 1024-pt radix-2 FFT along N, 8 columns/block ----------------
__global__ void k_fft1024s(float sign){
    extern __shared__ float2 sh[];   // [8][1025]
    const int tid = threadIdx.x;     // 512
    const int c = tid & 7, i0 = tid >> 3;
    int blk = blockIdx.x;
    int b = blk >> 6;
    int rem = blk & 63;
    int kblk = rem >> 4, j8 = rem & 15;
    float* base = g_fr + (size_t)b * 1024 * 1024 + kblk*256 + j8*8;

    #pragma unroll
    for (int r = 0; r < 16; r++){
        int n = i0 + r*64;
        int rv = __brev((unsigned)n) >> 22;
        float re = base[(size_t)n*1024 + c];
        float im = base[(size_t)n*1024 + 128 + c];
        sh[c*1025 + rv] = make_float2(re, im);
    }
    __syncthreads();
    for (int len = 2; len <= 1024; len <<= 1){
        int half = len >> 1;
        float w0 = sign * 6.283185307179586f / (float)len;
        #pragma unroll 2
        for (int r = 0; r < 8; r++){
            int bf = i0 + r*64;
            int j = bf & (half - 1);
            int i1 = ((bf & ~(half - 1)) << 1) | j;
            float s, cc;
            __sincosf(w0 * (float)j, &s, &cc);
            float2 av = sh[c*1025 + i1];
            float2 bv = sh[c*1025 + i1 + half];
            float2 t = make_float2(bv.x*cc - bv.y*s, bv.x*s + bv.y*cc);
            sh[c*1025 + i1]        = make_float2(av.x + t.x, av.y + t.y);
            sh[c*1025 + i1 + half] = make_float2(av.x - t.x, av.y - t.y);
        }
        __syncthreads();
    }
    const float sc = 0.015625f;
    #pragma unroll
    for (int r = 0; r < 16; r++){
        int n = i0 + r*64;
        float2 v = sh[c*1025 + n];
        base[(size_t)n*1024 + c]       = v.x * sc;
        base[(size_t)n*1024 + 128 + c] = v.y * sc;
    }
}

// ---------------- inverse 4-point DFT along NB, real part, add into out ----------------
__global__ void k_fft4_inv_add(float* __restrict__ out){
    int idx = blockIdx.x * blockDim.x + threadIdx.x;
    if (idx >= ROWS * 128) return;
    int j = idx & 127, row = idx >> 7;
    const float* q = g_fr + (size_t)row * 1024 + j;
    float r0 = q[0];
    float r1 = q[256], i1 = q[384];
    float r2 = q[512];
    float r3 = q[768], i3 = q[896];
    float* o = out + (size_t)row * DIM + j;
    o[0]   += r0 + r1 + r2 + r3;
    o[128] += r0 - i1 - r2 + i3;
    o[256] += r0 - r1 + r2 - r3;
    o[384] += r0 + i1 - r2 - i3;
}

// ---------------- host launch ----------------
extern "C" void kernel_launch(void* const* d_in, const int* in_sizes, int n_in,
                              void* d_out, int out_size){
    const float* x_in      = (const float*)d_in[0];
    const float* ln_w      = (const float*)d_in[1];
    const float* ln_b      = (const float*)d_in[2];
    const float* in_proj_w = (const float*)d_in[3];
    const float* conv_w    = (const float*)d_in[4];
    const float* conv_b    = (const float*)d_in[5];
    const float* x_proj_w  = (const float*)d_in[6];
    const float* dt_proj_w = (const float*)d_in[7];
    const float* dt_proj_b = (const float*)d_in[8];
    const float* A_log     = (const float*)d_in[9];
    const float* Dv        = (const float*)d_in[10];
    const float* out_proj_w= (const float*)d_in[11];
    const float* norm2_w   = (const float*)d_in[12];
    const float* norm2_b   = (const float*)d_in[13];
    const float* cw1       = (const float*)d_in[14];
    const float* cw2       = (const float*)d_in[15];
    const float* cb1       = (const float*)d_in[16];
    const float* cb2       = (const float*)d_in[17];
    float* xout = (float*)d_out;

    float *p_ln, *p_xz, *p_xmc, *p_proj, *p_dt, *p_y, *p_fr, *p_r1, *p_W1, *p_W2, *p_b1, *p_b2;
    __nv_bfloat16 *p_wie, *p_woe, *p_wde, *p_w1e, *p_w2e;
    cudaGetSymbolAddress((void**)&p_ln,   g_ln);
    cudaGetSymbolAddress((void**)&p_xz,   g_xz);
    cudaGetSymbolAddress((void**)&p_xmc,  g_xmc);
    cudaGetSymbolAddress((void**)&p_proj, g_proj);
    cudaGetSymbolAddress((void**)&p_dt,   g_dt);
    cudaGetSymbolAddress((void**)&p_y,    g_y);
    cudaGetSymbolAddress((void**)&p_fr,   g_fr);
    cudaGetSymbolAddress((void**)&p_r1,   g_r1);
    cudaGetSymbolAddress((void**)&p_W1,   g_W1);
    cudaGetSymbolAddress((void**)&p_W2,   g_W2);
    cudaGetSymbolAddress((void**)&p_b1,   g_b1);
    cudaGetSymbolAddress((void**)&p_b2,   g_b2);
    cudaGetSymbolAddress((void**)&p_wie,  g_wie);
    cudaGetSymbolAddress((void**)&p_woe,  g_woe);
    cudaGetSymbolAddress((void**)&p_wde,  g_wde);
    cudaGetSymbolAddress((void**)&p_w1e,  g_w1e);
    cudaGetSymbolAddress((void**)&p_w2e,  g_w2e);

    cudaFuncSetAttribute(k_fft1024s, cudaFuncAttributeMaxDynamicSharedMemorySize, 8*1025*8);

    cudaMemcpyAsync(xout, x_in, (size_t)ROWS*DIM*sizeof(float), cudaMemcpyDeviceToDevice, 0);

    // weight prep (once per launch)
    k_build<<<(4*256*256 + 255)/256, 256>>>(cw1, cw2, cb1, cb2);
    k_wext<<<(2048*512 + 255)/256, 256>>>(in_proj_w,  p_wie, 2048*512);
    k_wext<<<(512*1024 + 255)/256, 256>>>(out_proj_w, p_woe, 512*1024);
    k_wext<<<(1024*32 + 255)/256, 256>>>(dt_proj_w,   p_wde, 1024*32);
    k_wext<<<(4*256*256 + 255)/256, 256>>>(p_W1,      p_w1e, 4*256*256);
    k_wext<<<(4*256*256 + 255)/256, 256>>>(p_W2,      p_w2e, 4*256*256);

    for (int blk = 0; blk < 2; blk++){
        // ---- Mamba ----
        k_layernorm<<<ROWS, 256>>>(xout, ln_w, ln_b, p_ln);
        k_hgemm<0><<<dim3(16,16,1), 256>>>(1024,
            p_ln, DIM, 0, p_wie, 1024, 0, p_xz, 2*DI, 0, nullptr, 0);
        k_conv_silu<<<(ROWS*DI + 255)/256, 256>>>(conv_w, conv_b);
        k_gemm_t<64,32,32,4,4><<<dim3(5,32,1), 128>>>(DI,
            p_xmc, DI, x_proj_w, DI, p_proj, 160);
        k_hgemm<1><<<dim3(8,16,1), 256>>>(64,
            p_proj, 160, 0, p_wde, 64, 0, p_dt, DI, 0, dt_proj_b, 0);
        k_scan<<<512, 128>>>(A_log);
        k_gate<<<(ROWS*DI + 255)/256, 256>>>(Dv);
        k_hgemm<2><<<dim3(4,16,1), 256>>>(2048,
            p_y, DI, 0, p_woe, 2048, 0, xout, DIM, 0, nullptr, 0);

        // ---- EinFFT ----
        k_layernorm<<<ROWS, 256>>>(xout, norm2_w, norm2_b, p_ln);
        k_fft4_fwd<<<(ROWS*128 + 255)/256, 256>>>();
        k_fft1024s<<<128, 512, 8*1025*8>>>(-1.f);
        k_hgemm<3><<<dim3(2,16,4), 256>>>(512,
            p_fr, 1024, 256, p_w1e, 512, 256*512, p_r1, 1024, 256, p_b1, 256);
        k_hgemm<4><<<dim3(2,16,4), 256>>>(512,
            p_r1, 1024, 256, p_w2e, 512, 256*512, p_fr, 1024, 256, p_b2, 256);
        k_fft1024s<<<128, 512, 8*1025*8>>>(1.f);
        k_fft4_inv_add<<<(ROWS*128 + 255)/256, 256>>>(xout);
    }
}